// round 17
// baseline (speedup 1.0000x reference)
#include <cuda_runtime.h>
#include <cuda_fp16.h>
#include <cstdint>
#include <cstddef>

// VectorQuantizer on GB300 (sm_103a)
// fp16 HFMA2 coarse scan (572us proven) + MARGIN 0.5 flag +
// BATCHED exact fp32 rescore (codebook shared across 32 pixels/CTA).
// z_e: (16,256,64,64) fp32 ; embedding: (1024,256) fp32

#define NEMB 1024
#define EDIM 256
#define HW   4096
#define NPIX 65536
#define NC   16777216

#define MARGIN  0.5f
#define FLAGCAP 65536

// smem: 3 stages x (A 8KB + B 8KB) + e2 4KB = 52KB
#define STGSZ  16384
#define SM_E2  (3 * STGSZ)
#define SM_TOT (3 * STGSZ + 4096)

// ---- device scratch ----
__device__ __align__(128) uint32_t g_AT2[(size_t)EDIM * NPIX];  // [k][pix] dup'd half2
__device__ __align__(128) uint32_t g_BT2[EDIM * (NEMB / 2)];    // [k][codepair] half2
__device__ __align__(16) float  g_e2[NEMB];
__device__ int    g_idx[NPIX];
__device__ double g_part[2048];
__device__ int    g_nflag;
__device__ int    g_flag[FLAGCAP];

#define FMA2(d, a, b) asm("fma.rn.f32x2 %0, %1, %2, %0;" : "+l"(d) : "l"(a), "l"(b))

static __device__ __forceinline__ void unpack2(unsigned long long v, float& lo, float& hi) {
    unsigned int a, b;
    asm("mov.b64 {%0, %1}, %2;" : "=r"(a), "=r"(b) : "l"(v));
    lo = __uint_as_float(a);
    hi = __uint_as_float(b);
}
static __device__ __forceinline__ uint32_t s2u(const void* p) {
    uint32_t a;
    asm("{ .reg .u64 t; cvta.to.shared.u64 t, %1; cvt.u32.u64 %0, t; }" : "=r"(a) : "l"(p));
    return a;
}
static __device__ __forceinline__ void cpa16(uint32_t dst, const void* src) {
    asm volatile("cp.async.cg.shared.global [%0], [%1], 16;" :: "r"(dst), "l"(src));
}
static __device__ __forceinline__ uint32_t hfma2u(uint32_t a, uint32_t b, uint32_t c) {
    __half2 r = __hfma2(*reinterpret_cast<__half2*>(&a),
                        *reinterpret_cast<__half2*>(&b),
                        *reinterpret_cast<__half2*>(&c));
    return *reinterpret_cast<uint32_t*>(&r);
}
static __device__ __forceinline__ uint32_t dup_h(float x) {
    __half h = __float2half_rn(x);
    uint16_t u = *reinterpret_cast<uint16_t*>(&h);
    return (uint32_t)u | ((uint32_t)u << 16);
}
static __device__ __forceinline__ uint32_t pair_h(float lo, float hi) {
    __half2 h = __floats2half2_rn(lo, hi);
    return *reinterpret_cast<uint32_t*>(&h);
}

// ============================================================
// K1: per-code squared norms (exact fp32). One warp per code.
// ============================================================
__global__ void k_e2(const float* __restrict__ emb) {
    int warp = (blockIdx.x * blockDim.x + threadIdx.x) >> 5;
    int lane = threadIdx.x & 31;
    if (warp >= NEMB) return;
    const float4* row = reinterpret_cast<const float4*>(emb + (size_t)warp * EDIM);
    float s = 0.f;
    #pragma unroll
    for (int i = lane; i < EDIM / 4; i += 32) {
        float4 v = row[i];
        s += v.x * v.x + v.y * v.y + v.z * v.z + v.w * v.w;
    }
    #pragma unroll
    for (int o = 16; o; o >>= 1) s += __shfl_xor_sync(0xFFFFFFFFu, s, o);
    if (lane == 0) g_e2[warp] = s;
}

// ============================================================
// K2: transpose embedding -> g_BT2[k][codepair] half2
// ============================================================
__global__ __launch_bounds__(256) void k_bt2(const float* __restrict__ emb) {
    __shared__ float tile[32][33];
    const int t  = threadIdx.x;
    const int tx = t & 31;
    const int ty = t >> 5;
    const int c0 = blockIdx.x << 5;
    const int k0 = blockIdx.y << 5;
    #pragma unroll
    for (int i = 0; i < 4; ++i)
        tile[ty + i * 8][tx] = emb[(size_t)(c0 + ty + i * 8) * EDIM + k0 + tx];
    __syncthreads();
    #pragma unroll
    for (int it = 0; it < 2; ++it) {
        int idx = t + (it << 8);
        int k = idx >> 4, pr = idx & 15;
        g_BT2[(size_t)(k0 + k) * (NEMB / 2) + (c0 >> 1) + pr] =
            pair_h(tile[2 * pr][k], tile[2 * pr + 1][k]);
    }
}

// ============================================================
// K3: z_e -> g_AT2[k][pix] duplicated half2 (layout-preserving)
// ============================================================
__global__ __launch_bounds__(256) void k_prep_x(const float* __restrict__ z) {
    if (blockIdx.x == 0 && threadIdx.x == 0) g_nflag = 0;
    const float4* z4 = reinterpret_cast<const float4*>(z);
    int tid = blockIdx.x * blockDim.x + threadIdx.x;
    #pragma unroll
    for (int it = 0; it < 8; ++it) {
        int i = tid + it * 524288;
        float4 v = z4[i];
        int lin = i << 2;
        int hw = lin & 4095;
        int c  = (lin >> 12) & 255;
        int b  = lin >> 20;
        uint4 w;
        w.x = dup_h(v.x); w.y = dup_h(v.y); w.z = dup_h(v.z); w.w = dup_h(v.w);
        *reinterpret_cast<uint4*>(&g_AT2[(size_t)c * NPIX + b * HW + hw]) = w;
    }
}

// ============================================================
// K4: fp16 HFMA2 coarse + per-step fp32 promotion + top-2 argmin.
// (byte-identical to R15's 572us kernel)
// ============================================================
__global__ __launch_bounds__(256, 2) void k_argmin_hf() {
    extern __shared__ char smem[];
    const uint32_t sbase = s2u(smem);
    float* se2 = reinterpret_cast<float*>(smem + SM_E2);

    const int t  = threadIdx.x;
    const int tx = t & 15;
    const int ty = t >> 4;
    const int pix0 = blockIdx.x << 6;

    #pragma unroll
    for (int i = 0; i < 4; ++i) se2[t + (i << 8)] = g_e2[t + (i << 8)];

    #pragma unroll
    for (int p = 0; p < 2; ++p) {
        const uint32_t ba = sbase + p * STGSZ;
        #pragma unroll
        for (int i = 0; i < 4; ++i) {
            int idx = t + (i << 8);
            if (idx < 512) {
                int kk = idx >> 4, seg = idx & 15;
                cpa16(ba + kk * 256 + (seg << 4),
                      &g_AT2[(size_t)(p * 32 + kk) * NPIX + pix0 + (seg << 2)]);
            } else {
                int gb = idx - 512, kk = gb >> 4, seg = gb & 15;
                cpa16(ba + 8192 + kk * 256 + (seg << 4),
                      &g_BT2[(size_t)(p * 32 + kk) * (NEMB / 2) + (seg << 2)]);
            }
        }
        asm volatile("cp.async.commit_group;" ::: "memory");
    }

    float bv[4], b2[4];
    int   bi[4];
    #pragma unroll
    for (int i = 0; i < 4; ++i) { bv[i] = 3.402823466e38f; b2[i] = 3.402823466e38f; bi[i] = 0; }

    uint32_t acc[4][4];
    float facc[4][8];
    #pragma unroll
    for (int i = 0; i < 4; ++i) {
        #pragma unroll
        for (int j = 0; j < 4; ++j) acc[i][j] = 0u;
        #pragma unroll
        for (int j = 0; j < 8; ++j) facc[i][j] = 0.f;
    }

    #pragma unroll 1
    for (int g = 0; g < 64; ++g) {
        if (g < 63) {
            asm volatile("cp.async.wait_group 1;" ::: "memory");
        } else {
            asm volatile("cp.async.wait_group 0;" ::: "memory");
        }
        __syncthreads();

        if (g + 2 < 64) {
            const int g2 = g + 2;
            const int cc2 = g2 >> 3, kc2 = g2 & 7;
            const uint32_t ba = sbase + (g2 % 3) * STGSZ;
            #pragma unroll
            for (int i = 0; i < 4; ++i) {
                int idx = t + (i << 8);
                if (idx < 512) {
                    int kk = idx >> 4, seg = idx & 15;
                    cpa16(ba + kk * 256 + (seg << 4),
                          &g_AT2[(size_t)(kc2 * 32 + kk) * NPIX + pix0 + (seg << 2)]);
                } else {
                    int gb = idx - 512, kk = gb >> 4, seg = gb & 15;
                    cpa16(ba + 8192 + kk * 256 + (seg << 4),
                          &g_BT2[(size_t)(kc2 * 32 + kk) * (NEMB / 2) + cc2 * 64 + (seg << 2)]);
                }
            }
            asm volatile("cp.async.commit_group;" ::: "memory");
        }

        const char* pA = smem + (g % 3) * STGSZ;
        const char* pB = pA + 8192;

        #pragma unroll 8
        for (int kk = 0; kk < 32; ++kk) {
            uint4 av = *reinterpret_cast<const uint4*>(pA + kk * 256 + (ty << 4));
            uint4 bw = *reinterpret_cast<const uint4*>(pB + kk * 256 + (tx << 4));
            uint32_t ad[4] = {av.x, av.y, av.z, av.w};
            uint32_t bb[4] = {bw.x, bw.y, bw.z, bw.w};
            #pragma unroll
            for (int i = 0; i < 4; ++i)
                #pragma unroll
                for (int j = 0; j < 4; ++j)
                    acc[i][j] = hfma2u(ad[i], bb[j], acc[i][j]);
        }

        #pragma unroll
        for (int i = 0; i < 4; ++i)
            #pragma unroll
            for (int j = 0; j < 4; ++j) {
                uint32_t a = acc[i][j];
                acc[i][j] = 0u;
                float2 f = __half22float2(*reinterpret_cast<__half2*>(&a));
                facc[i][2 * j]     += f.x;
                facc[i][2 * j + 1] += f.y;
            }

        if ((g & 7) == 7) {
            const int cbase = ((g >> 3) << 7) + (tx << 3);
            #pragma unroll
            for (int i = 0; i < 4; ++i) {
                #pragma unroll
                for (int j = 0; j < 8; ++j) {
                    float sc = fmaf(-2.f, facc[i][j], se2[cbase + j]);
                    facc[i][j] = 0.f;
                    int c = cbase + j;
                    if (sc < bv[i]) { b2[i] = bv[i]; bv[i] = sc; bi[i] = c; }
                    else if (sc < b2[i]) b2[i] = sc;
                }
            }
        }
    }

    #pragma unroll
    for (int o = 1; o <= 8; o <<= 1) {
        #pragma unroll
        for (int i = 0; i < 4; ++i) {
            float ov = __shfl_xor_sync(0xFFFFFFFFu, bv[i], o);
            float o2 = __shfl_xor_sync(0xFFFFFFFFu, b2[i], o);
            int   oi = __shfl_xor_sync(0xFFFFFFFFu, bi[i], o);
            if (ov < bv[i] || (ov == bv[i] && oi < bi[i])) {
                b2[i] = fminf(bv[i], o2);
                bv[i] = ov; bi[i] = oi;
            } else {
                b2[i] = fminf(b2[i], ov);
            }
        }
    }
    if (tx == 0) {
        #pragma unroll
        for (int i = 0; i < 4; ++i) {
            int prow = pix0 + (ty << 2) + i;
            g_idx[prow] = bi[i];
            if (b2[i] - bv[i] < MARGIN) {
                int pos = atomicAdd(&g_nflag, 1);
                if (pos < FLAGCAP) g_flag[pos] = prow;
            }
        }
    }
}

// ============================================================
// K5: BATCHED exact fp32 rescore.
// CTA handles 32 flagged pixels: x staged in smem (pitch 260 = conflict-
// free float4), 8 warps sweep codebook with warp-uniform e loads.
// Thread (p = t&31, grp = t>>5) scores codes [grp*128, grp*128+128) for
// pixel p; group-ascending final merge keeps lowest index on ties.
// ============================================================
__global__ __launch_bounds__(256) void k_fix(const float* __restrict__ z,
                                             const float* __restrict__ emb) {
    __shared__ float sx[32 * 260];
    __shared__ float rv[256];
    __shared__ int   ri[256];

    const int t = threadIdx.x;
    int nf = g_nflag; if (nf > FLAGCAP) nf = FLAGCAP;

    for (int base = blockIdx.x * 32; base < nf; base += gridDim.x * 32) {
        const int cnt = min(32, nf - base);

        // ---- stage x for this batch ----
        #pragma unroll 4
        for (int idx = t; idx < 32 * 256; idx += 256) {
            int p = idx & 31, k = idx >> 5;
            if (p < cnt) {
                int pix = g_flag[base + p];
                const float* zb = z + (((size_t)(pix >> 12)) << 20) + (pix & 4095);
                sx[p * 260 + k] = zb[(size_t)k * HW];
            }
        }
        __syncthreads();

        const int p   = t & 31;
        const int grp = t >> 5;
        float bv = 3.402823466e38f;
        int   bi = grp << 7;

        if (p < cnt) {
            const unsigned long long* xp =
                reinterpret_cast<const unsigned long long*>(&sx[p * 260]);
            #pragma unroll 1
            for (int ci = 0; ci < 128; ++ci) {
                const int c = (grp << 7) + ci;
                const unsigned long long* ep =
                    reinterpret_cast<const unsigned long long*>(emb + (size_t)c * EDIM);
                unsigned long long a01 = 0ULL, a23 = 0ULL;
                #pragma unroll 16
                for (int q = 0; q < 128; q += 2) {
                    FMA2(a01, xp[q],     ep[q]);
                    FMA2(a23, xp[q + 1], ep[q + 1]);
                }
                float l0, h0, l1, h1;
                unpack2(a01, l0, h0);
                unpack2(a23, l1, h1);
                float dot = (l0 + h0) + (l1 + h1);
                float sc = g_e2[c] - 2.f * dot;
                if (sc < bv) { bv = sc; bi = c; }
            }
        }
        rv[t] = bv; ri[t] = bi;
        __syncthreads();

        // final merge over the 8 code groups (ascending -> lowest idx on tie)
        if (grp == 0 && p < cnt) {
            float best = rv[p]; int besti = ri[p];
            #pragma unroll
            for (int g = 1; g < 8; ++g) {
                float v = rv[p + (g << 5)];
                int   i = ri[p + (g << 5)];
                if (v < best) { best = v; besti = i; }
            }
            g_idx[g_flag[base + p]] = besti;
        }
        __syncthreads();
    }
}

// ============================================================
// K6: gather z_q, write z_q_st = z_e + (z_q - z_e), loss partials
// ============================================================
__global__ __launch_bounds__(256)
void k_gather(const float* __restrict__ z, const float* __restrict__ emb,
              float* __restrict__ out) {
    __shared__ float sE[32 * 260];
    __shared__ float swarp[8];
    const int t = threadIdx.x;
    const int pix0 = blockIdx.x << 5;

    #pragma unroll
    for (int it = 0; it < 8; ++it) {
        int slot = t + (it << 8);
        int p = slot >> 6, c4 = slot & 63;
        int idx = g_idx[pix0 + p];
        float4 v = *reinterpret_cast<const float4*>(emb + (size_t)idx * EDIM + (c4 << 2));
        *reinterpret_cast<float4*>(&sE[p * 260 + (c4 << 2)]) = v;
    }
    __syncthreads();

    const float* zb = z   + (((size_t)(pix0 >> 12)) << 20) + (pix0 & 4095);
    float*       ob = out + (((size_t)(pix0 >> 12)) << 20) + (pix0 & 4095);

    float lsum = 0.f;
    #pragma unroll
    for (int it = 0; it < 8; ++it) {
        int slot = t + (it << 8);
        int hw = slot & 31, c4 = slot >> 5;
        float4 e = *reinterpret_cast<const float4*>(&sE[hw * 260 + (c4 << 2)]);
        float ev[4] = {e.x, e.y, e.z, e.w};
        #pragma unroll
        for (int j = 0; j < 4; ++j) {
            size_t gg = (size_t)((c4 << 2) + j) * HW + hw;
            float ze = zb[gg];
            float d = ev[j] - ze;
            ob[gg] = ze + d;
            lsum += d * d;
        }
    }
    #pragma unroll
    for (int o = 16; o; o >>= 1) lsum += __shfl_xor_sync(0xFFFFFFFFu, lsum, o);
    if ((t & 31) == 0) swarp[t >> 5] = lsum;
    __syncthreads();
    if (t == 0) {
        double s = 0.0;
        #pragma unroll
        for (int w = 0; w < 8; ++w) s += (double)swarp[w];
        g_part[blockIdx.x] = s;
    }
}

// ============================================================
// K7: loss finalize
// ============================================================
__global__ void k_loss(float* __restrict__ out, int out_size) {
    __shared__ double sd[256];
    int t = threadIdx.x;
    double s = 0.0;
    for (int i = t; i < 2048; i += 256) s += g_part[i];
    sd[t] = s;
    __syncthreads();
    for (int o = 128; o; o >>= 1) {
        if (t < o) sd[t] += sd[t + o];
        __syncthreads();
    }
    if (t == 0 && out_size > NC)
        out[NC] = (float)(0.25 * sd[0] / (double)NC);
}

// ============================================================
extern "C" void kernel_launch(void* const* d_in, const int* in_sizes, int n_in,
                              void* d_out, int out_size) {
    const float* z   = (const float*)d_in[0];
    const float* emb = (const float*)d_in[1];
    float* out = (float*)d_out;

    cudaFuncSetAttribute(k_argmin_hf, cudaFuncAttributeMaxDynamicSharedMemorySize, SM_TOT);

    k_e2     <<<128, 256>>>(emb);
    {
        dim3 grid(32, 8);
        k_bt2<<<grid, 256>>>(emb);
    }
    k_prep_x   <<<2048, 256>>>(z);
    k_argmin_hf<<<1024, 256, SM_TOT>>>();
    k_fix      <<<256,  256>>>(z, emb);
    k_gather   <<<2048, 256>>>(z, emb, out);
    k_loss     <<<1,    256>>>(out, out_size);
}